// round 4
// baseline (speedup 1.0000x reference)
#include <cuda_runtime.h>

// Problem constants (fixed by the reference)
#define BB     256
#define DD     1024
#define NSLOT  200000
#define KK     64
#define NCHUNK 148
#define CHUNK  ((NSLOT + NCHUNK - 1) / NCHUNK)   // 1352
#define TN     64                                 // slot rows per smem tile

typedef unsigned long long ull;

// Static device scratch (no allocations allowed). 16B-aligned: accessed
// through 8/16-byte vector types.
__device__ __align__(16) float g_cueout[BB * KK];                 // 64 KB
__device__ __align__(16) float g_accpart[NCHUNK * BB * KK];       // ~9.7 MB
__device__ __align__(16) float g_denpart[NCHUNK * BB];            // ~151 KB
__device__ __align__(16) float g_ret[BB * KK];                    // 64 KB

// ---------------------------------------------------------------- PTX helpers
__device__ __forceinline__ ull ffma2(ull a, ull b, ull c) {
    ull d;
    asm("fma.rn.f32x2 %0, %1, %2, %3;" : "=l"(d) : "l"(a), "l"(b), "l"(c));
    return d;
}
__device__ __forceinline__ ull fadd2(ull a, ull b) {
    ull d;
    asm("add.rn.f32x2 %0, %1, %2;" : "=l"(d) : "l"(a), "l"(b));
    return d;
}
// 16B shared load -> two packed f32 pairs. volatile: must not move across barriers.
__device__ __forceinline__ void lds2(ull& a, ull& b, unsigned addr) {
    asm volatile("ld.shared.v2.b64 {%0, %1}, [%2];"
                 : "=l"(a), "=l"(b) : "r"(addr));
}
__device__ __forceinline__ unsigned s2u(const void* p) {
    return (unsigned)__cvta_generic_to_shared(p);
}
__device__ __forceinline__ void cpasync16(unsigned dst, const void* src, int srcsz) {
    asm volatile("cp.async.cg.shared.global [%0], [%1], 16, %2;"
                 :: "r"(dst), "l"(src), "r"(srcsz));
}
__device__ __forceinline__ void cpcommit() {
    asm volatile("cp.async.commit_group;");
}
template <int N>
__device__ __forceinline__ void cpwait() {
    asm volatile("cp.async.wait_group %0;" :: "n"(N));
}

// ------------------------------------------------- kernel 1: cue projection
// cue_outer[b,k] = sum_d cue[b,d] * w_cue[k,d]   (w_cue is (K, D) row-major)
// grid 64 x 256 threads: 4 batch rows per CTA, thread = (b_local, k).
__global__ __launch_bounds__(256)
void k_cueproj(const float* __restrict__ cue, const float* __restrict__ wcue) {
    int b = blockIdx.x * 4 + (threadIdx.x >> 6);
    int k = threadIdx.x & 63;
    const float4* cr = (const float4*)(cue + (size_t)b * DD);
    const float4* wr = (const float4*)(wcue + (size_t)k * DD);
    float a0 = 0.f, a1 = 0.f, a2 = 0.f, a3 = 0.f;
#pragma unroll 8
    for (int j = 0; j < DD / 4; j++) {
        float4 c4 = cr[j];
        float4 w4 = wr[j];
        a0 += c4.x * w4.x; a1 += c4.y * w4.y;
        a2 += c4.z * w4.z; a3 += c4.w * w4.w;
    }
    g_cueout[b * KK + k] = (a0 + a1) + (a2 + a3);
}

// ------------------------------------------------- kernel 2: fused sim/softmax/readout
// 512 threads/CTA; a PAIR of threads owns one batch row:
//   b = tid>>1, h = tid&1. Thread (b,h) owns dim chunks {8*j2+4h .. 8*j2+4h+3}
//   (16B-interleaved so the pair's LDS hit adjacent banks: conflict-free).
// Per slot row: each thread half-dots (8 ffma2), shfl.bfly(1) combines,
// both compute e = exp(s)*p, each accumulates its 32 dims (16 ffma2) from the
// register-cached row. Row loaded from smem ONCE per thread (8 LDS.128).
// ~116 regs/thread -> fits 512 threads with no spills.
// No max-subtraction: sim ~ N(0, 8); far below fp32 exp overflow (~88).
__global__ __launch_bounds__(512, 1)
void k_main(const float* __restrict__ slot, const float* __restrict__ prio) {
    __shared__ __align__(16) float4 shs[2][TN * 16];   // 2 x 16 KB slot tiles
    __shared__ __align__(16) float  shp[2][TN];        // priority tiles

    const int c   = blockIdx.x;
    const int tid = threadIdx.x;
    const int b   = tid >> 1;
    const int h   = tid & 1;
    const int n0  = c * CHUNK;
    const int cnt = min(CHUNK, NSLOT - n0);   // > 0 for all 148 chunks

    // q: this thread's 32 dims (interleaved 16B chunks) as 16 packed pairs
    ull q2[16];
    {
        const ull* qp = (const ull*)(g_cueout + b * KK);
#pragma unroll
        for (int j2 = 0; j2 < 8; j2++) {
            q2[2 * j2]     = qp[4 * j2 + 2 * h];
            q2[2 * j2 + 1] = qp[4 * j2 + 2 * h + 1];
        }
    }
    ull acc2[16];
#pragma unroll
    for (int j = 0; j < 16; j++) acc2[j] = 0ull;
    float den = 0.f;

    const unsigned sb0 = s2u(&shs[0][0]);
    const unsigned sb1 = s2u(&shs[1][0]);
    const unsigned hoff = h * 16;
    const int nTiles = (cnt + TN - 1) / TN;

    auto loadTile = [&](int t) {
        const int buf  = t & 1;
        const int base = n0 + t * TN;
        // slot rows: TN*256B = 16KB = 1024 x 16B chunks over 512 threads
#pragma unroll
        for (int it = 0; it < 2; it++) {
            int idx = tid + it * 512;
            int row = idx >> 4;
            int gn  = base + row;
            bool ok = (gn < NSLOT);
            const char* src = (const char*)slot +
                              (ok ? ((size_t)gn * 256 + (size_t)(idx & 15) * 16) : 0);
            unsigned dst = (buf ? sb1 : sb0) + idx * 16;
            cpasync16(dst, src, ok ? 16 : 0);
        }
        // priority: TN floats = 256B = 16 x 16B chunks (threads 0..15)
        if (tid < 16) {
            int gn  = base + tid * 4;
            int rem = NSLOT - gn;
            int sz  = rem >= 4 ? 16 : (rem > 0 ? rem * 4 : 0);
            const char* src = (const char*)prio + (sz ? (size_t)gn * 4 : 0);
            unsigned dst = s2u(&shp[buf][0]) + tid * 16;
            cpasync16(dst, src, sz);
        }
    };

    loadTile(0);
    cpcommit();

    for (int t = 0; t < nTiles; t++) {
        if (t + 1 < nTiles) {
            loadTile(t + 1);
            cpcommit();
            cpwait<1>();
        } else {
            cpwait<0>();
        }
        __syncthreads();

        const int rows = min(TN, cnt - t * TN);
        const unsigned tb = (t & 1) ? sb1 : sb0;
        const float* pp = shp[t & 1];

#pragma unroll 1
        for (int i = 0; i < rows; i++) {
            const unsigned ra = tb + i * 256 + hoff;

            // ---- load this thread's 32 dims once, half-dot (2 chains)
            ull r2[16];
            ull s0 = 0ull, s1 = 0ull;
#pragma unroll
            for (int j2 = 0; j2 < 8; j2++) {
                lds2(r2[2 * j2], r2[2 * j2 + 1], ra + j2 * 32);
                s0 = ffma2(q2[2 * j2],     r2[2 * j2],     s0);
                s1 = ffma2(q2[2 * j2 + 1], r2[2 * j2 + 1], s1);
            }
            ull ss = fadd2(s0, s1);
            unsigned ulo, uhi;
            asm("mov.b64 {%0, %1}, %2;" : "=r"(ulo), "=r"(uhi) : "l"(ss));
            float sh = __uint_as_float(ulo) + __uint_as_float(uhi);
            float s  = sh + __shfl_xor_sync(0xffffffffu, sh, 1);

            float e = __expf(s) * pp[i];
            den += e;

            unsigned eu = __float_as_uint(e);
            ull e2;
            asm("mov.b64 %0, {%1, %1};" : "=l"(e2) : "r"(eu));

            // ---- accumulate this thread's 32 dims from the register cache
#pragma unroll
            for (int j = 0; j < 16; j++)
                acc2[j] = ffma2(e2, r2[j], acc2[j]);
        }
        __syncthreads();  // protect buffer about to be overwritten by next preload
    }

    // write per-chunk partials (scattered 16B chunks matching ownership)
    {
        ull* ap = (ull*)(g_accpart + ((size_t)c * BB + b) * KK);
#pragma unroll
        for (int j2 = 0; j2 < 8; j2++) {
            ap[4 * j2 + 2 * h]     = acc2[2 * j2];
            ap[4 * j2 + 2 * h + 1] = acc2[2 * j2 + 1];
        }
        if (h == 0) g_denpart[c * BB + b] = den;
    }
}

// ------------------------------------------------- kernel 3: cross-chunk reduce
// grid 64 x 256: thread = (b_local, k), 4 batch rows per CTA.
__global__ __launch_bounds__(256)
void k_reduce() {
    int b = blockIdx.x * 4 + (threadIdx.x >> 6);
    int k = threadIdx.x & 63;
    float s = 0.f, dn = 0.f;
#pragma unroll 4
    for (int c = 0; c < NCHUNK; c++) {
        s  += g_accpart[((size_t)c * BB + b) * KK + k];
        dn += g_denpart[c * BB + b];
    }
    g_ret[b * KK + k] = s / dn;
}

// ------------------------------------------------- kernel 4: decoder
// out[b,d] = sum_k ret[b,k] * w_dec[d,k]   (w_dec is (D, K) row-major)
// grid 64 x 256: 4 batch rows per CTA -> each w_dec float4 feeds 16 FMAs.
// seg loop NOT unrolled (keeps live float4 loads bounded -> no spills).
__global__ __launch_bounds__(256)
void k_dec(const float* __restrict__ wdec, float* __restrict__ out) {
    __shared__ float r[4][KK];
    int b0 = blockIdx.x * 4;
    {
        int bl = threadIdx.x >> 6, k = threadIdx.x & 63;
        r[bl][k] = g_ret[(b0 + bl) * KK + k];
    }
    __syncthreads();
#pragma unroll 1
    for (int seg = 0; seg < 4; seg++) {
        int d = threadIdx.x + seg * 256;
        const float4* w4 = (const float4*)(wdec + (size_t)d * KK);
        float a0 = 0.f, a1 = 0.f, a2 = 0.f, a3 = 0.f;
#pragma unroll
        for (int j = 0; j < 16; j++) {
            float4 w = w4[j];
            a0 += r[0][4 * j] * w.x + r[0][4 * j + 1] * w.y
                + r[0][4 * j + 2] * w.z + r[0][4 * j + 3] * w.w;
            a1 += r[1][4 * j] * w.x + r[1][4 * j + 1] * w.y
                + r[1][4 * j + 2] * w.z + r[1][4 * j + 3] * w.w;
            a2 += r[2][4 * j] * w.x + r[2][4 * j + 1] * w.y
                + r[2][4 * j + 2] * w.z + r[2][4 * j + 3] * w.w;
            a3 += r[3][4 * j] * w.x + r[3][4 * j + 1] * w.y
                + r[3][4 * j + 2] * w.z + r[3][4 * j + 3] * w.w;
        }
        out[(size_t)(b0 + 0) * DD + d] = a0;
        out[(size_t)(b0 + 1) * DD + d] = a1;
        out[(size_t)(b0 + 2) * DD + d] = a2;
        out[(size_t)(b0 + 3) * DD + d] = a3;
    }
}

// ------------------------------------------------- launch
extern "C" void kernel_launch(void* const* d_in, const int* in_sizes, int n_in,
                              void* d_out, int out_size) {
    const float* cue  = (const float*)d_in[0];  // (B, D)
    const float* slot = (const float*)d_in[1];  // (N, K)
    const float* prio = (const float*)d_in[2];  // (N,)
    const float* wcue = (const float*)d_in[3];  // (K, D)
    const float* wdec = (const float*)d_in[4];  // (D, K)
    float* out = (float*)d_out;                 // (B, D)

    k_cueproj<<<64, 256>>>(cue, wcue);
    k_main<<<NCHUNK, 512>>>(slot, prio);
    k_reduce<<<64, 256>>>();
    k_dec<<<64, 256>>>(wdec, out);
}

// round 6
// speedup vs baseline: 1.5912x; 1.5912x over previous
#include <cuda_runtime.h>

// Problem constants (fixed by the reference)
#define BB     256
#define DD     1024
#define NSLOT  200000
#define KK     64
#define NCHUNK 148
#define CHUNK  ((NSLOT + NCHUNK - 1) / NCHUNK)   // 1352
#define TN     64                                 // slot rows per smem tile

typedef unsigned long long ull;

// Static device scratch (no allocations allowed). 16B-aligned: accessed
// through 8/16-byte vector types.
__device__ __align__(16) float g_cueout[BB * KK];                 // 64 KB
__device__ __align__(16) float g_accpart[NCHUNK * BB * KK];       // ~9.7 MB
__device__ __align__(16) float g_denpart[NCHUNK * BB];            // ~151 KB
__device__ __align__(16) float g_ret[BB * KK];                    // 64 KB

// ---------------------------------------------------------------- PTX helpers
__device__ __forceinline__ ull ffma2(ull a, ull b, ull c) {
    ull d;
    asm("fma.rn.f32x2 %0, %1, %2, %3;" : "=l"(d) : "l"(a), "l"(b), "l"(c));
    return d;
}
__device__ __forceinline__ ull fadd2(ull a, ull b) {
    ull d;
    asm("add.rn.f32x2 %0, %1, %2;" : "=l"(d) : "l"(a), "l"(b));
    return d;
}
// 16B shared load -> two packed f32 pairs. volatile: must not move across barriers.
__device__ __forceinline__ void lds2(ull& a, ull& b, unsigned addr) {
    asm volatile("ld.shared.v2.b64 {%0, %1}, [%2];"
                 : "=l"(a), "=l"(b) : "r"(addr));
}
__device__ __forceinline__ unsigned s2u(const void* p) {
    return (unsigned)__cvta_generic_to_shared(p);
}
__device__ __forceinline__ void cpasync16(unsigned dst, const void* src, int srcsz) {
    asm volatile("cp.async.cg.shared.global [%0], [%1], 16, %2;"
                 :: "r"(dst), "l"(src), "r"(srcsz));
}
__device__ __forceinline__ void cpcommit() {
    asm volatile("cp.async.commit_group;");
}
template <int N>
__device__ __forceinline__ void cpwait() {
    asm volatile("cp.async.wait_group %0;" :: "n"(N));
}

// ------------------------------------------------- kernel 1: cue projection
// cue_outer[b,k] = sum_d cue[b,d] * w_cue[k,d]   (w_cue is (K, D) row-major)
// grid 64 x 256 threads: 4 batch rows per CTA, thread = (b_local, k).
__global__ __launch_bounds__(256)
void k_cueproj(const float* __restrict__ cue, const float* __restrict__ wcue) {
    int b = blockIdx.x * 4 + (threadIdx.x >> 6);
    int k = threadIdx.x & 63;
    const float4* cr = (const float4*)(cue + (size_t)b * DD);
    const float4* wr = (const float4*)(wcue + (size_t)k * DD);
    float a0 = 0.f, a1 = 0.f, a2 = 0.f, a3 = 0.f;
#pragma unroll 8
    for (int j = 0; j < DD / 4; j++) {
        float4 c4 = cr[j];
        float4 w4 = wr[j];
        a0 += c4.x * w4.x; a1 += c4.y * w4.y;
        a2 += c4.z * w4.z; a3 += c4.w * w4.w;
    }
    g_cueout[b * KK + k] = (a0 + a1) + (a2 + a3);
}

// ------------------------------------------------- kernel 2: fused sim/softmax/readout
// One CTA per N-chunk; thread t owns batch row t end-to-end (256 threads).
// Explicit 2-row software pipeline: rows i and i+1 processed together with
// 8 independent dot chains and interleaved accumulates -> double the ILP of
// the serial version while staying ~180 regs (no spills at 256 thr).
// No max-subtraction: sim ~ N(0, 8); far below fp32 exp overflow (~88).
__global__ __launch_bounds__(256, 1)
void k_main(const float* __restrict__ slot, const float* __restrict__ prio) {
    __shared__ __align__(16) float4 shs[2][TN * 16];   // 2 x 16 KB slot tiles
    __shared__ __align__(16) float  shp[2][TN];        // priority tiles

    const int c   = blockIdx.x;
    const int tid = threadIdx.x;
    const int n0  = c * CHUNK;
    const int cnt = min(CHUNK, NSLOT - n0);   // > 0 for all 148 chunks

    // q (64 floats) as 32 packed pairs
    ull q2[32];
    {
        const ull* qp = (const ull*)(g_cueout + tid * KK);
#pragma unroll
        for (int j = 0; j < 32; j++) q2[j] = qp[j];
    }
    ull acc2[32];
#pragma unroll
    for (int j = 0; j < 32; j++) acc2[j] = 0ull;
    float den = 0.f;

    const unsigned sb0 = s2u(&shs[0][0]);
    const unsigned sb1 = s2u(&shs[1][0]);
    const int nTiles = (cnt + TN - 1) / TN;

    auto loadTile = [&](int t) {
        const int buf  = t & 1;
        const int base = n0 + t * TN;
        // slot rows: TN*256B = 16KB = 1024 x 16B chunks over 256 threads
#pragma unroll
        for (int it = 0; it < 4; it++) {
            int idx = tid + it * 256;
            int row = idx >> 4;
            int gn  = base + row;
            bool ok = (gn < NSLOT);
            const char* src = (const char*)slot +
                              (ok ? ((size_t)gn * 256 + (size_t)(idx & 15) * 16) : 0);
            unsigned dst = (buf ? sb1 : sb0) + idx * 16;
            cpasync16(dst, src, ok ? 16 : 0);
        }
        // priority: TN floats = 256B = 16 x 16B chunks (threads 0..15)
        if (tid < 16) {
            int gn  = base + tid * 4;
            int rem = NSLOT - gn;
            int sz  = rem >= 4 ? 16 : (rem > 0 ? rem * 4 : 0);
            const char* src = (const char*)prio + (sz ? (size_t)gn * 4 : 0);
            unsigned dst = s2u(&shp[buf][0]) + tid * 16;
            cpasync16(dst, src, sz);
        }
    };

    loadTile(0);
    cpcommit();

    for (int t = 0; t < nTiles; t++) {
        if (t + 1 < nTiles) {
            loadTile(t + 1);
            cpcommit();
            cpwait<1>();
        } else {
            cpwait<0>();
        }
        __syncthreads();

        const int rows = min(TN, cnt - t * TN);
        const unsigned tb = (t & 1) ? sb1 : sb0;
        const float* pp = shp[t & 1];

        int i = 0;
#pragma unroll 1
        for (; i + 1 < rows; i += 2) {
            const unsigned raA = tb + i * 256;
            const unsigned raB = raA + 256;

            // ---- dual-row dot: 8 independent f32x2 chains
            ull sA0 = 0ull, sA1 = 0ull, sA2 = 0ull, sA3 = 0ull;
            ull sB0 = 0ull, sB1 = 0ull, sB2 = 0ull, sB3 = 0ull;
#pragma unroll
            for (int jj = 0; jj < 8; jj++) {
                ull a0, a1, b0, b1;
                lds2(a0, a1, raA + jj * 32);
                lds2(b0, b1, raB + jj * 32);
                sA0 = ffma2(q2[4 * jj],     a0, sA0);
                sA1 = ffma2(q2[4 * jj + 1], a1, sA1);
                sB0 = ffma2(q2[4 * jj],     b0, sB0);
                sB1 = ffma2(q2[4 * jj + 1], b1, sB1);
                ull a2, a3, b2, b3;
                lds2(a2, a3, raA + jj * 32 + 16);
                lds2(b2, b3, raB + jj * 32 + 16);
                sA2 = ffma2(q2[4 * jj + 2], a2, sA2);
                sA3 = ffma2(q2[4 * jj + 3], a3, sA3);
                sB2 = ffma2(q2[4 * jj + 2], b2, sB2);
                sB3 = ffma2(q2[4 * jj + 3], b3, sB3);
            }
            ull ssA = fadd2(fadd2(sA0, sA2), fadd2(sA1, sA3));
            ull ssB = fadd2(fadd2(sB0, sB2), fadd2(sB1, sB3));
            unsigned lA, hA, lB, hB;
            asm("mov.b64 {%0, %1}, %2;" : "=r"(lA), "=r"(hA) : "l"(ssA));
            asm("mov.b64 {%0, %1}, %2;" : "=r"(lB), "=r"(hB) : "l"(ssB));
            float sA = __uint_as_float(lA) + __uint_as_float(hA);
            float sB = __uint_as_float(lB) + __uint_as_float(hB);

            float eA = __expf(sA) * pp[i];
            float eB = __expf(sB) * pp[i + 1];
            den += eA + eB;

            unsigned euA = __float_as_uint(eA), euB = __float_as_uint(eB);
            ull eA2, eB2;
            asm("mov.b64 %0, {%1, %1};" : "=l"(eA2) : "r"(euA));
            asm("mov.b64 %0, {%1, %1};" : "=l"(eB2) : "r"(euB));

            // ---- dual-row accumulate (chain depth 2, 16 independent groups)
#pragma unroll
            for (int jj = 0; jj < 16; jj++) {
                ull a0, a1, b0, b1;
                lds2(a0, a1, raA + jj * 16);
                lds2(b0, b1, raB + jj * 16);
                acc2[2 * jj]     = ffma2(eA2, a0, acc2[2 * jj]);
                acc2[2 * jj + 1] = ffma2(eA2, a1, acc2[2 * jj + 1]);
                acc2[2 * jj]     = ffma2(eB2, b0, acc2[2 * jj]);
                acc2[2 * jj + 1] = ffma2(eB2, b1, acc2[2 * jj + 1]);
            }
        }
        // tail (rows is even for this problem size; kept for safety)
        if (i < rows) {
            const unsigned ra = tb + i * 256;
            ull s0 = 0ull, s1 = 0ull, s2 = 0ull, s3 = 0ull;
#pragma unroll
            for (int jj = 0; jj < 8; jj++) {
                ull a0, a1, a2, a3;
                lds2(a0, a1, ra + jj * 32);
                lds2(a2, a3, ra + jj * 32 + 16);
                s0 = ffma2(q2[4 * jj],     a0, s0);
                s1 = ffma2(q2[4 * jj + 1], a1, s1);
                s2 = ffma2(q2[4 * jj + 2], a2, s2);
                s3 = ffma2(q2[4 * jj + 3], a3, s3);
            }
            ull ss = fadd2(fadd2(s0, s2), fadd2(s1, s3));
            unsigned lo, hi;
            asm("mov.b64 {%0, %1}, %2;" : "=r"(lo), "=r"(hi) : "l"(ss));
            float s = __uint_as_float(lo) + __uint_as_float(hi);
            float e = __expf(s) * pp[i];
            den += e;
            unsigned eu = __float_as_uint(e);
            ull e2;
            asm("mov.b64 %0, {%1, %1};" : "=l"(e2) : "r"(eu));
#pragma unroll
            for (int jj = 0; jj < 16; jj++) {
                ull a0, a1;
                lds2(a0, a1, ra + jj * 16);
                acc2[2 * jj]     = ffma2(e2, a0, acc2[2 * jj]);
                acc2[2 * jj + 1] = ffma2(e2, a1, acc2[2 * jj + 1]);
            }
        }
        __syncthreads();  // protect buffer about to be overwritten by next preload
    }

    // write per-chunk partials
    ull* ap = (ull*)g_accpart + ((size_t)c * BB + tid) * 32;
#pragma unroll
    for (int j = 0; j < 32; j++) ap[j] = acc2[j];
    g_denpart[c * BB + tid] = den;
}

// ------------------------------------------------- kernel 3: cross-chunk reduce
// grid 64 x 256: thread = (b_local, k), 4 batch rows per CTA.
__global__ __launch_bounds__(256)
void k_reduce() {
    int b = blockIdx.x * 4 + (threadIdx.x >> 6);
    int k = threadIdx.x & 63;
    float s = 0.f, dn = 0.f;
#pragma unroll 4
    for (int c = 0; c < NCHUNK; c++) {
        s  += g_accpart[((size_t)c * BB + b) * KK + k];
        dn += g_denpart[c * BB + b];
    }
    g_ret[b * KK + k] = s / dn;
}

// ------------------------------------------------- kernel 4: decoder
// out[b,d] = sum_k ret[b,k] * w_dec[d,k]   (w_dec is (D, K) row-major)
// grid 64 x 256: 4 batch rows per CTA (measured 16.0us in R3 run).
__global__ __launch_bounds__(256)
void k_dec(const float* __restrict__ wdec, float* __restrict__ out) {
    __shared__ float r[4][KK];
    int b0 = blockIdx.x * 4;
    {
        int bl = threadIdx.x >> 6, k = threadIdx.x & 63;
        r[bl][k] = g_ret[(b0 + bl) * KK + k];
    }
    __syncthreads();
#pragma unroll
    for (int seg = 0; seg < 4; seg++) {
        int d = threadIdx.x + seg * 256;
        const float4* w4 = (const float4*)(wdec + (size_t)d * KK);
        float a0 = 0.f, a1 = 0.f, a2 = 0.f, a3 = 0.f;
#pragma unroll
        for (int j = 0; j < 16; j++) {
            float4 w = w4[j];
            a0 += r[0][4 * j] * w.x + r[0][4 * j + 1] * w.y
                + r[0][4 * j + 2] * w.z + r[0][4 * j + 3] * w.w;
            a1 += r[1][4 * j] * w.x + r[1][4 * j + 1] * w.y
                + r[1][4 * j + 2] * w.z + r[1][4 * j + 3] * w.w;
            a2 += r[2][4 * j] * w.x + r[2][4 * j + 1] * w.y
                + r[2][4 * j + 2] * w.z + r[2][4 * j + 3] * w.w;
            a3 += r[3][4 * j] * w.x + r[3][4 * j + 1] * w.y
                + r[3][4 * j + 2] * w.z + r[3][4 * j + 3] * w.w;
        }
        out[(size_t)(b0 + 0) * DD + d] = a0;
        out[(size_t)(b0 + 1) * DD + d] = a1;
        out[(size_t)(b0 + 2) * DD + d] = a2;
        out[(size_t)(b0 + 3) * DD + d] = a3;
    }
}

// ------------------------------------------------- launch
extern "C" void kernel_launch(void* const* d_in, const int* in_sizes, int n_in,
                              void* d_out, int out_size) {
    const float* cue  = (const float*)d_in[0];  // (B, D)
    const float* slot = (const float*)d_in[1];  // (N, K)
    const float* prio = (const float*)d_in[2];  // (N,)
    const float* wcue = (const float*)d_in[3];  // (K, D)
    const float* wdec = (const float*)d_in[4];  // (D, K)
    float* out = (float*)d_out;                 // (B, D)

    k_cueproj<<<64, 256>>>(cue, wcue);
    k_main<<<NCHUNK, 256>>>(slot, prio);
    k_reduce<<<64, 256>>>();
    k_dec<<<64, 256>>>(wdec, out);
}